// round 6
// baseline (speedup 1.0000x reference)
#include <cuda_runtime.h>

// ---------------------------------------------------------------------------
// MeanAggregator: out[r, :] = mean over edges e with row_ids[e]==r of
//                 features[neigh_ids[e], :]   (row_ids sorted ascending)
//
// R6 = R5, but agg feature loads switched from 1x LDG.128 (4 lines within one
//      instr, all at 2.07 cyc/wf replay rate) to 2x LDG.64 per edge (2 lines
//      each; first wavefront of each LDG services at the 1.0 cyc/wf cross-LDG
//      rate). Predicted ~6.1 vs 8.3 cyc/edge on the L1tex queue.
//      Lane owns dims {2*lane, 2*lane+1} and {64+2*lane, 64+2*lane+1}.
// ---------------------------------------------------------------------------

#define MAX_ROWS 131072
#define D_FEAT   128

__device__ int g_offsets[MAX_ROWS + 1];

// int64 detection: neigh_ids uniform-random in [0,100000) -> for int64 LE the
// odd 32-bit words are all zero; for int32 essentially never. Warp ballot.
__device__ __forceinline__ bool detect_is64(const void* neigh, int lane) {
    const unsigned* w = (const unsigned*)neigh;
    unsigned hiw = __ldg(&w[2 * lane + 1]);
    unsigned m = __ballot_sync(0xFFFFFFFFu, hiw == 0u);
    return __popc(m) >= 28;
}

template <typename IdxT>
__device__ __forceinline__ int row_at_cg(const void* p, int i) {
    return (int)__ldcg(((const IdxT*)p) + i);
}

// ---- segment boundaries from sorted row_ids.
__global__ __launch_bounds__(256) void bounds_kernel(const void* __restrict__ rows_v,
                                                     const void* __restrict__ neigh_v,
                                                     int E, int nrows) {
    int i    = blockIdx.x * blockDim.x + threadIdx.x;
    int lane = threadIdx.x & 31;
    bool is64 = detect_is64(neigh_v, lane);

    int r = 0;
    bool valid = (i < E);
    if (valid)
        r = is64 ? row_at_cg<long long>(rows_v, i) : row_at_cg<int>(rows_v, i);

    int rp = __shfl_up_sync(0xFFFFFFFFu, r, 1);
    if (lane == 0) {
        rp = (i == 0) ? -1
                      : (is64 ? row_at_cg<long long>(rows_v, i - 1)
                              : row_at_cg<int>(rows_v, i - 1));
    }
    if (!valid) return;

    for (int q = rp + 1; q <= r; q++) g_offsets[q] = i;
    if (i == E - 1) {
        for (int q = r + 1; q <= nrows; q++) g_offsets[q] = E;
    }
}

// ---- main gather+mean: one warp per row, lane owns 2x float2.
// Index fetch: lanes 0..3 load the next 4 indices coalesced, broadcast by shfl.
template <typename IdxT>
__device__ __forceinline__ void aggregate_row(const float2* __restrict__ feats,
                                              const IdxT* __restrict__ neigh,
                                              int row, int lane, int lo, int hi,
                                              float2* __restrict__ out) {
    // feats viewed as float2[ node ][ 64 ]; lane covers slot `lane` (dims
    // 2l,2l+1) and slot `32+lane` (dims 64+2l, 64+2l+1).
    float ax = 0.f, ay = 0.f, bx = 0.f, by = 0.f;   // edge-pair accum set A
    float cx = 0.f, cy = 0.f, dx = 0.f, dy = 0.f;   // edge-pair accum set B
    int e = lo;
    for (; e + 4 <= hi; e += 4) {
        int my = (lane < 4) ? (int)__ldg(neigh + e + lane) : 0;
        size_t n0 = (size_t)__shfl_sync(0xFFFFFFFFu, my, 0) * (D_FEAT / 2);
        size_t n1 = (size_t)__shfl_sync(0xFFFFFFFFu, my, 1) * (D_FEAT / 2);
        size_t n2 = (size_t)__shfl_sync(0xFFFFFFFFu, my, 2) * (D_FEAT / 2);
        size_t n3 = (size_t)__shfl_sync(0xFFFFFFFFu, my, 3) * (D_FEAT / 2);
        float2 p0 = __ldg(feats + n0 + lane);
        float2 q0 = __ldg(feats + n0 + 32 + lane);
        float2 p1 = __ldg(feats + n1 + lane);
        float2 q1 = __ldg(feats + n1 + 32 + lane);
        float2 p2 = __ldg(feats + n2 + lane);
        float2 q2 = __ldg(feats + n2 + 32 + lane);
        float2 p3 = __ldg(feats + n3 + lane);
        float2 q3 = __ldg(feats + n3 + 32 + lane);
        ax += p0.x + p1.x;  ay += p0.y + p1.y;
        bx += q0.x + q1.x;  by += q0.y + q1.y;
        cx += p2.x + p3.x;  cy += p2.y + p3.y;
        dx += q2.x + q3.x;  dy += q2.y + q3.y;
    }
    for (; e < hi; e++) {
        size_t n = (size_t)__ldg(neigh + e) * (D_FEAT / 2);
        float2 p = __ldg(feats + n + lane);
        float2 q = __ldg(feats + n + 32 + lane);
        ax += p.x; ay += p.y;
        bx += q.x; by += q.y;
    }
    ax += cx; ay += cy; bx += dx; by += dy;
    int cnt = hi - lo;
    float inv = 1.0f / (float)(cnt > 0 ? cnt : 1);
    float2 r0 = make_float2(ax * inv, ay * inv);
    float2 r1 = make_float2(bx * inv, by * inv);
    float2* o = out + (size_t)row * (D_FEAT / 2);
    __stcs(o + lane, r0);
    __stcs(o + 32 + lane, r1);
}

__global__ __launch_bounds__(256) void agg_kernel(const float2* __restrict__ feats,
                                                  const void* __restrict__ neigh_v,
                                                  int nrows,
                                                  float2* __restrict__ out) {
    int gwarp = (blockIdx.x * blockDim.x + threadIdx.x) >> 5;
    int lane  = threadIdx.x & 31;
    if (gwarp >= nrows) return;
    bool is64 = detect_is64(neigh_v, lane);
    int lo = g_offsets[gwarp];
    int hi = g_offsets[gwarp + 1];
    if (is64)
        aggregate_row<long long>(feats, (const long long*)neigh_v, gwarp, lane, lo, hi, out);
    else
        aggregate_row<int>(feats, (const int*)neigh_v, gwarp, lane, lo, hi, out);
}

extern "C" void kernel_launch(void* const* d_in, const int* in_sizes, int n_in,
                              void* d_out, int out_size) {
    const float* feats = (const float*)d_in[0];
    const void*  neigh = d_in[1];
    const void*  rows  = d_in[2];
    int E     = in_sizes[1];
    int nrows = out_size / D_FEAT;

    bounds_kernel<<<(E + 255) / 256, 256>>>(rows, neigh, E, nrows);

    int total_threads = nrows * 32;
    agg_kernel<<<(total_threads + 255) / 256, 256>>>(
        (const float2*)feats, neigh, nrows, (float2*)d_out);
}